// round 1
// baseline (speedup 1.0000x reference)
#include <cuda_runtime.h>

#define B_ 4096
#define T_ 256
#define C_ 64
#define H_ 16
#define D_ 16
#define S_ 10

// Scratch: xw[b][t][h] = LN(cov) @ rnn_wx + rnn_b   (64 MB)
__device__ float g_xw[(long)B_ * T_ * H_];

__device__ __forceinline__ float fsig(float x) {
    // 1/(1+exp(-x)) via exp2 — accurate to ~1e-7
    return 1.0f / (1.0f + exp2f(-1.4426950408889634f * x));
}
__device__ __forceinline__ float ftanh(float x) {
    // tanh(x) = 2/(1+exp(-2x)) - 1
    return 2.0f / (1.0f + exp2f(-2.8853900817779268f * x)) - 1.0f;
}

// ---------------------------------------------------------------------------
// Kernel 1: fused LayerNorm + x @ Wx + b, LN folded into post-scaling:
//   xw_j = rs * (cov . Wg_:,j) - rs*mu*S1_j + S2_j
//   Wg[c][j] = gamma[c]*Wx[c][j];  S1_j = sum_c Wg;  S2_j = sum_c beta_c*Wx + b_j
// One thread per (b,t) row. Weights broadcast from smem (conflict-free).
// ---------------------------------------------------------------------------
__global__ void __launch_bounds__(256) k_ln_xw(
    const float* __restrict__ cov,
    const float* __restrict__ gamma,
    const float* __restrict__ beta,
    const float* __restrict__ wx,
    const float* __restrict__ rnn_b)
{
    __shared__ float sWg[C_ * H_];
    __shared__ float sS1[H_];
    __shared__ float sS2[H_];

    int tid = threadIdx.x;
    for (int i = tid; i < C_ * H_; i += blockDim.x) {
        int c = i >> 4;
        sWg[i] = gamma[c] * wx[i];
    }
    __syncthreads();
    if (tid < H_) {
        float s1 = 0.f, s2 = 0.f;
        for (int c = 0; c < C_; c++) {
            s1 += sWg[c * H_ + tid];
            s2 += beta[c] * wx[c * H_ + tid];
        }
        sS1[tid] = s1;
        sS2[tid] = s2 + rnn_b[tid];
    }
    __syncthreads();

    const float4* wg4 = reinterpret_cast<const float4*>(sWg);

    long r = (long)blockIdx.x * blockDim.x + tid;   // row = b*T + t
    if (r >= (long)B_ * T_) return;

    const float4* cv = reinterpret_cast<const float4*>(cov + r * C_);

    float acc[H_];
#pragma unroll
    for (int j = 0; j < H_; j++) acc[j] = 0.f;
    float sum = 0.f, sq = 0.f;

#pragma unroll
    for (int c4 = 0; c4 < C_ / 4; c4++) {
        float4 v = cv[c4];
        float xs[4] = {v.x, v.y, v.z, v.w};
#pragma unroll
        for (int k = 0; k < 4; k++) {
            float xc = xs[k];
            sum += xc;
            sq  += xc * xc;
            int c = c4 * 4 + k;
            float4 w0 = wg4[c * 4 + 0];
            float4 w1 = wg4[c * 4 + 1];
            float4 w2 = wg4[c * 4 + 2];
            float4 w3 = wg4[c * 4 + 3];
            acc[0]  += xc * w0.x; acc[1]  += xc * w0.y; acc[2]  += xc * w0.z; acc[3]  += xc * w0.w;
            acc[4]  += xc * w1.x; acc[5]  += xc * w1.y; acc[6]  += xc * w1.z; acc[7]  += xc * w1.w;
            acc[8]  += xc * w2.x; acc[9]  += xc * w2.y; acc[10] += xc * w2.z; acc[11] += xc * w2.w;
            acc[12] += xc * w3.x; acc[13] += xc * w3.y; acc[14] += xc * w3.z; acc[15] += xc * w3.w;
        }
    }

    float mu  = sum * (1.0f / 64.0f);
    float var = sq  * (1.0f / 64.0f) - mu * mu;
    float rs  = rsqrtf(var + 1e-3f);
    float rm  = rs * mu;

    float4 o[4];
    float* op = reinterpret_cast<float*>(o);
#pragma unroll
    for (int j = 0; j < H_; j++) op[j] = rs * acc[j] - rm * sS1[j] + sS2[j];

    float4* outp = reinterpret_cast<float4*>(g_xw + r * H_);
    outp[0] = o[0]; outp[1] = o[1]; outp[2] = o[2]; outp[3] = o[3];
}

// ---------------------------------------------------------------------------
// Kernel 2: sequential scan over T. 16-lane team per batch (2 teams/warp).
// Lane q owns h-component q, driver-component q, and weight columns in regs.
// Cash-budget transforms distributed (one sigmoid/lane), arithmetic replicated.
// ---------------------------------------------------------------------------
__global__ void __launch_bounds__(256) k_scan(
    const float* __restrict__ states_seq,
    const float* __restrict__ wh,
    const float* __restrict__ d1w,
    const float* __restrict__ d1b,
    const float* __restrict__ d2w,
    const float* __restrict__ d2b,
    float* __restrict__ out)
{
    const unsigned FULL = 0xffffffffu;
    int tid = threadIdx.x;
    int q = tid & 15;
    int b = blockIdx.x * (blockDim.x >> 4) + (tid >> 4);

    // Weight columns (column q of each matrix)
    float whc[H_], d1c[H_], d2c[H_];
#pragma unroll
    for (int i = 0; i < H_; i++) {
        whc[i] = wh[i * H_ + q];
        d1c[i] = d1w[i * H_ + q];
        d2c[i] = d2w[i * D_ + q];
    }
    float b1q = d1b[q], b2q = d2b[q];

    // Cash state s0 = states_seq[b, 0, :], replicated across team lanes
    const float* s0 = states_seq + (long)b * T_ * S_;
    float rev  = s0[0], cash = s0[1], ar = s0[2], inv = s0[3], ppe = s0[4],
          ap   = s0[5], debt = s0[6], eqty = s0[7], re = s0[8], oth = s0[9];

    // Per-lane driver transform params: tv = sig(arg)*mul + add
    // lane0: tanh(d)*0.2 = (2*sig(2d)-1)*0.2 -> sig(2d)*0.4 - 0.2
    float mul = 1.0f, add = 0.0f;
    if      (q == 0) { mul = 0.4f;  add = -0.2f; }
    else if (q == 2) { mul = 0.5f;  }
    else if (q == 3) { mul = 0.1f;  }
    else if (q == 4) { mul = 0.2f;  }
    else if (q == 8) { mul = 0.35f; }
    else if (q == 9) { mul = 0.1f;  }
    float argscale = (q == 0) ? 2.0f : 1.0f;

    const float* xwp = g_xw + (long)b * T_ * H_;
    float* st_out = out + (long)b * (T_ - 1) * S_;
    float* is_out = out + (long)B_ * (T_ - 1) * S_ + (long)b * (T_ - 1) * 7;

    float h = 0.0f;

    for (int t = 0; t < T_; t++) {
        // RNN step: h = tanh(xw_t + h @ Wh)
        float acc = xwp[t * H_ + q];
#pragma unroll
        for (int i = 0; i < H_; i++)
            acc += __shfl_sync(FULL, h, i, 16) * whc[i];
        h = ftanh(acc);

        if (t >= 1) {
            // driver MLP: d = tanh(h @ W1 + b1) @ W2 + b2
            float aa = b1q;
#pragma unroll
            for (int i = 0; i < H_; i++)
                aa += __shfl_sync(FULL, h, i, 16) * d1c[i];
            float a = ftanh(aa);
            float dd = b2q;
#pragma unroll
            for (int i = 0; i < H_; i++)
                dd += __shfl_sync(FULL, a, i, 16) * d2c[i];

            // distributed transform + broadcast
            float tv = fsig(argscale * dd) * mul + add;
            float tr0 = __shfl_sync(FULL, tv, 0, 16);
            float tr1 = __shfl_sync(FULL, tv, 1, 16);
            float tr2 = __shfl_sync(FULL, tv, 2, 16);
            float tr3 = __shfl_sync(FULL, tv, 3, 16);
            float tr4 = __shfl_sync(FULL, tv, 4, 16);
            float tr5 = __shfl_sync(FULL, tv, 5, 16);
            float tr6 = __shfl_sync(FULL, tv, 6, 16);
            float tr7 = __shfl_sync(FULL, tv, 7, 16);
            float tr8 = __shfl_sync(FULL, tv, 8, 16);
            float tr9 = __shfl_sync(FULL, tv, 9, 16);

            // cash budget (replicated across lanes)
            float nrev  = rev * (1.0f + tr0);
            float cogs  = tr1 * nrev;
            float opex  = tr2 * nrev;
            float dep   = tr3 * ppe;
            float intr  = tr9 * debt;
            float ebt   = nrev - cogs - opex - dep - intr;
            float tax   = tr8 * fmaxf(ebt, 0.0f);
            float ni    = ebt - tax;
            float arn   = tr5 * nrev;
            float invn  = tr6 * cogs;
            float apn   = tr7 * cogs;
            float capex = tr4 * nrev;
            float ppen  = ppe + capex - dep;
            float cashn = cash + ni + dep - capex - (arn - ar) - (invn - inv) + (apn - ap);
            float ren   = re + ni;

            int o = t - 1;
            // states_pred component q
            float sv = nrev;
            if      (q == 1) sv = cashn;
            else if (q == 2) sv = arn;
            else if (q == 3) sv = invn;
            else if (q == 4) sv = ppen;
            else if (q == 5) sv = apn;
            else if (q == 6) sv = debt;
            else if (q == 7) sv = eqty;
            else if (q == 8) sv = ren;
            else if (q == 9) sv = oth;
            if (q < S_) st_out[o * S_ + q] = sv;

            // is_pred component q
            float iv = nrev;
            if      (q == 1) iv = cogs;
            else if (q == 2) iv = opex;
            else if (q == 3) iv = dep;
            else if (q == 4) iv = intr;
            else if (q == 5) iv = tax;
            else if (q == 6) iv = ni;
            if (q < 7) is_out[o * 7 + q] = iv;

            rev = nrev; cash = cashn; ar = arn; inv = invn;
            ppe = ppen; ap = apn; re = ren;
        }
    }
}

extern "C" void kernel_launch(void* const* d_in, const int* in_sizes, int n_in,
                              void* d_out, int out_size)
{
    const float* states = (const float*)d_in[0];
    const float* cov    = (const float*)d_in[1];
    const float* gamma  = (const float*)d_in[2];
    const float* beta   = (const float*)d_in[3];
    const float* wx     = (const float*)d_in[4];
    const float* wh     = (const float*)d_in[5];
    const float* rnn_b  = (const float*)d_in[6];
    const float* d1w    = (const float*)d_in[7];
    const float* d1b    = (const float*)d_in[8];
    const float* d2w    = (const float*)d_in[9];
    const float* d2b    = (const float*)d_in[10];
    float* out = (float*)d_out;

    k_ln_xw<<<(B_ * T_) / 256, 256>>>(cov, gamma, beta, wx, rnn_b);
    k_scan<<<B_ / 16, 256>>>(states, wh, d1w, d1b, d2w, d2b, out);
}